// round 3
// baseline (speedup 1.0000x reference)
#include <cuda_runtime.h>
#include <cuda_bf16.h>

// RocketConv: 84 ternary dilated depthwise kernels.
// y_k[t] = -S(t) + 3*(s_a + s_b + s_c),  s_j = x[t + 4j - 16],  S = sum_j s_j
// Output layout (after the reference's double reshape) is flat (B, C, K, T):
//   out[((b*16 + c)*84 + k)*4096 + t]
//
// Grid: (4 segments of 1024 t) x (256 rows = b*16+c). Block: 256 threads,
// each thread produces 4 consecutive t for all 84 kernels (float4 stores).

#define T_LEN   4096
#define SEG     1024
#define NTHREADS 256
#define HALO    16
#define TILE_F  (SEG + 2 * HALO)   // 1056 floats

__global__ __launch_bounds__(NTHREADS)
void rocketconv_kernel(const float* __restrict__ x, float* __restrict__ out) {
    const int row = blockIdx.y;                 // b*16 + c
    const int seg = blockIdx.x * SEG;           // start t of this segment
    const float* __restrict__ xrow = x + (size_t)row * T_LEN;

    // Stage the row segment (+/- 16 halo, zero padded) into shared memory.
    __shared__ __align__(16) float tile[TILE_F];
    for (int i = threadIdx.x; i < TILE_F; i += NTHREADS) {
        const int g = seg - HALO + i;
        tile[i] = (g >= 0 && g < T_LEN) ? xrow[g] : 0.0f;
    }
    __syncthreads();

    // Thread handles t0..t0+3, t0 = seg + 4*tid.
    // Tap j for (t0+dt) is tile[4*tid + 4*j + dt] -> aligned float4 per tap.
    const int l = 4 * threadIdx.x;
    float4 tp[9];
    #pragma unroll
    for (int j = 0; j < 9; j++)
        tp[j] = *reinterpret_cast<const float4*>(&tile[l + 4 * j]);

    float4 S = make_float4(0.f, 0.f, 0.f, 0.f);
    #pragma unroll
    for (int j = 0; j < 9; j++) {
        S.x += tp[j].x; S.y += tp[j].y; S.z += tp[j].z; S.w += tp[j].w;
    }
    const float nSx = -S.x, nSy = -S.y, nSz = -S.z, nSw = -S.w;

    // Output base for k=0 at this thread's t0; k-stride = 4096 floats = 1024 float4s.
    float4* __restrict__ obase = reinterpret_cast<float4*>(
        out + (size_t)row * 84 * T_LEN + seg) + threadIdx.x;

    int k = 0;
    #pragma unroll
    for (int a = 0; a < 9; a++) {
        #pragma unroll
        for (int b = a + 1; b < 9; b++) {
            const float px = tp[a].x + tp[b].x;
            const float py = tp[a].y + tp[b].y;
            const float pz = tp[a].z + tp[b].z;
            const float pw = tp[a].w + tp[b].w;
            #pragma unroll
            for (int c = b + 1; c < 9; c++) {
                float4 r;
                r.x = fmaf(3.0f, px + tp[c].x, nSx);
                r.y = fmaf(3.0f, py + tp[c].y, nSy);
                r.z = fmaf(3.0f, pz + tp[c].z, nSz);
                r.w = fmaf(3.0f, pw + tp[c].w, nSw);
                // Streaming store: write-once 352 MB output, don't pollute L2.
                __stcs(obase + (size_t)k * (T_LEN / 4), r);
                k++;
            }
        }
    }
}

extern "C" void kernel_launch(void* const* d_in, const int* in_sizes, int n_in,
                              void* d_out, int out_size) {
    const float* x = (const float*)d_in[0];
    float* out = (float*)d_out;
    dim3 grid(T_LEN / SEG, 16 * 16);   // (4, 256)
    rocketconv_kernel<<<grid, NTHREADS>>>(x, out);
}